// round 16
// baseline (speedup 1.0000x reference)
#include <cuda_runtime.h>
#include <cuda_bf16.h>
#include <stdint.h>

// ============================================================
// Problem dims
// ============================================================
#define IN_F  4096
#define OUT_F 4096
#define BATCH 8192

#define BM 256
#define BN 128
#define BK 32
#define NK (IN_F / BK)          // 128 k-tiles
#define NPM (BATCH / BM)        // 32
#define NPN (OUT_F / BN)        // 32
#define TILE_GROUP 8
#define THREADS 256             // 8 warps: 4 (M) x 2 (N), warp tile 64x64
#define STAGES 4

#define NK16 (IN_F / 16)        // 256 k16 groups per row

// SMEM: [0..32) full mbar[4], [32..64) empty mbar[4], buffers at 128
#define SM_BUF0 128
#define SM_A_BYTES 32768
#define SM_B_BYTES 16384
#define STAGE_BYTES (SM_A_BYTES + SM_B_BYTES)        // 49152
#define SMEM_TOTAL (SM_BUF0 + STAGES * STAGE_BYTES)  // 196736

// per-refill global byte advance
#define A_STEP 128u             // raw x: 32 floats per k-tile per row
#define B_STEP 1024u            // 2 k16 groups * 32 lanes * 16 B

// fused prep block ranges (256 threads each): W pack + bias only
#define PREP_W_BLOCKS 16384
#define PREP_BLOCKS (PREP_W_BLOCKS + 16)

// ============================================================
// Scratch (X is consumed raw -- no XP array needed)
// ============================================================
__device__ float4 g_WP[(size_t)(OUT_F / 8) * NK16 * 32];
__device__ float  g_bias[OUT_F];

// ============================================================
// Helpers
// ============================================================
__device__ __forceinline__ float rnd_tf32(float f) {
    float r;
    asm("cvt.rna.tf32.f32 %0, %1;" : "=f"(r) : "f"(f));
    return r;
}

__device__ __forceinline__ uint32_t smem_u32(const void* p) {
    uint32_t a;
    asm("{ .reg .u64 t; cvta.to.shared.u64 t, %1; cvt.u32.u64 %0, t; }"
        : "=r"(a) : "l"(p));
    return a;
}

__device__ __forceinline__ void cp16(uint32_t saddr, const void* gptr) {
    asm volatile("cp.async.cg.shared.global [%0], [%1], 16;\n"
                 :: "r"(saddr), "l"(gptr));
}

__device__ __forceinline__ void mbar_init(uint32_t a, uint32_t cnt) {
    asm volatile("mbarrier.init.shared.b64 [%0], %1;" :: "r"(a), "r"(cnt) : "memory");
}
__device__ __forceinline__ void mbar_arrive(uint32_t a) {
    asm volatile("mbarrier.arrive.shared.b64 _, [%0];" :: "r"(a) : "memory");
}
__device__ __forceinline__ void mbar_wait(uint32_t addr, uint32_t parity) {
    asm volatile(
        "{\n\t.reg .pred P;\n\t"
        "WAIT_%=:\n\t"
        "mbarrier.try_wait.parity.acquire.cta.shared::cta.b64 P, [%0], %1, 0x989680;\n\t"
        "@P bra.uni DONE_%=;\n\t"
        "bra.uni WAIT_%=;\n\t"
        "DONE_%=:\n\t}"
        :: "r"(addr), "r"(parity) : "memory");
}
__device__ __forceinline__ void cp_async_arrive(uint32_t a) {
    asm volatile("cp.async.mbarrier.arrive.noinc.shared.b64 [%0];"
                 :: "r"(a) : "memory");
}

__device__ __forceinline__ void mma_tf32(float& c0, float& c1, float& c2, float& c3,
                                         uint32_t a0, uint32_t a1, uint32_t a2, uint32_t a3,
                                         uint32_t b0, uint32_t b1) {
    asm volatile(
        "mma.sync.aligned.m16n8k8.row.col.f32.tf32.tf32.f32 "
        "{%0,%1,%2,%3}, {%4,%5,%6,%7}, {%8,%9}, {%0,%1,%2,%3};"
        : "+f"(c0), "+f"(c1), "+f"(c2), "+f"(c3)
        : "r"(a0), "r"(a1), "r"(a2), "r"(a3), "r"(b0), "r"(b1));
}

// ============================================================
// Fused prep: W materialize + pack (k-permuted consecutive
// float4) | bias. X needs no prep (consumed raw by the GEMM).
// Pack: WP[col8][k16][lane=(g,t)] = w[n=col8*8+g, k=k16*16+4t .. 4t+3]
// ============================================================
__global__ void prep_fused(const float* __restrict__ mu,
                           const float* __restrict__ lv,
                           const float* __restrict__ eps,
                           const float* __restrict__ bmu,
                           const float* __restrict__ blv,
                           const float* __restrict__ beps) {
    int bid = blockIdx.x;
    if (bid < PREP_W_BLOCKS) {
        size_t i = (size_t)bid * 256 + threadIdx.x;          // 4194304
        int col8 = (int)(i >> 13);
        int rem  = (int)(i & 8191);
        int k16  = rem >> 5;
        int lane = rem & 31;
        int g = lane >> 2, t = lane & 3;
        size_t idx4 = (size_t)(col8 * 8 + g) * (IN_F / 4) + k16 * 4 + t;
        float4 m4 = reinterpret_cast<const float4*>(mu)[idx4];
        float4 l4 = reinterpret_cast<const float4*>(lv)[idx4];
        float4 e4 = reinterpret_cast<const float4*>(eps)[idx4];
        float4 v;
        v.x = rnd_tf32(m4.x + e4.x * __expf(0.5f * l4.x));
        v.y = rnd_tf32(m4.y + e4.y * __expf(0.5f * l4.y));
        v.z = rnd_tf32(m4.z + e4.z * __expf(0.5f * l4.z));
        v.w = rnd_tf32(m4.w + e4.w * __expf(0.5f * l4.w));
        g_WP[i] = v;
    } else {
        int i = (bid - PREP_W_BLOCKS) * 256 + threadIdx.x;
        if (i < OUT_F) g_bias[i] = bmu[i] + beps[i] * __expf(0.5f * blv[i]);
    }
}

// ============================================================
// GEMM: C[256,128] per CTA, 256 threads (8 warps = 4 x 2)
// warp tile 64 x 64, BK=32, 4-stage pipeline, refill 2 ahead,
// mainloop unrolled x4. A is loaded RAW from x (row-major,
// XOR-chunk-swizzled smem); k-permutation makes each thread's
// A fragment for a k16 group one LDS.128. B fragment-packed.
// ============================================================
__global__ void __launch_bounds__(THREADS, 1) gemm_kernel(const float* __restrict__ x,
                                                          float* __restrict__ out) {
    extern __shared__ char smem[];
    const uint32_t sb = smem_u32(smem);
    const int tid = threadIdx.x;
    const int wid = tid >> 5;
    const int lane = tid & 31;
    const int wm = wid >> 1;      // 0..3  (M, 64 rows)
    const int wn = wid & 1;       // 0..1  (N, 64 cols)
    const int gq = lane >> 2;
    const int tg = lane & 3;

    int pid = blockIdx.x;
    int grp = pid / (TILE_GROUP * NPN);
    int pin = pid % (TILE_GROUP * NPN);
    int pm  = grp * TILE_GROUP + (pin % TILE_GROUP);
    int pn  = pin / TILE_GROUP;
    const int m0 = pm * BM;
    const int n0 = pn * BN;
    const int n08 = n0 >> 3;

    // full[s] at sb + s*8, empty[s] at sb + 32 + s*8
    if (tid == 0) {
#pragma unroll
        for (int s = 0; s < STAGES; ++s) {
            mbar_init(sb + s * 8, 256);
            mbar_init(sb + 32 + s * 8, 8);
        }
    }
    __syncthreads();

    // ---- refill offsets ----
    // A: raw x, 16B chunks; dst swizzled chunk within 128B row
    uint32_t offA[8], dstA[8];
#pragma unroll
    for (int t = 0; t < 8; ++t) {
        int ca = tid + t * THREADS;           // 0..2047
        int r  = ca >> 3;                     // row 0..255
        int i2 = ca & 7;                      // chunk 0..7
        offA[t] = (uint32_t)((m0 + r) * (IN_F * 4) + i2 * 16);
        int sw = i2 ^ (((r & 1) << 2) ^ ((r >> 1) & 3));
        dstA[t] = (uint32_t)(r * 128 + sw * 16);
    }
    uint32_t offB[4];
#pragma unroll
    for (int t = 0; t < 4; ++t) {
        int cb = tid + t * THREADS;
        int c8l = cb >> 6;
        int inner = cb & 63;
        offB[t] = (uint32_t)(((((n08 + c8l) * NK16) + (inner >> 5)) * 32
                              + (inner & 31)) * 16);
    }
    const char* gXb = (const char*)x;
    const char* gWb = (const char*)g_WP;

    auto load_A = [&](uint32_t abase) {
#pragma unroll
        for (int t = 0; t < 8; ++t)
            cp16(abase + dstA[t], gXb + offA[t]);
#pragma unroll
        for (int t = 0; t < 8; ++t) offA[t] += A_STEP;
    };
    auto load_B = [&](uint32_t bbase) {
#pragma unroll
        for (int t = 0; t < 4; ++t)
            cp16(bbase + (uint32_t)(tid + t * THREADS) * 16u, gWb + offB[t]);
#pragma unroll
        for (int t = 0; t < 4; ++t) offB[t] += B_STEP;
    };

    // prologue: load stages 0 and 1
    load_A(sb + SM_BUF0);
    load_B(sb + SM_BUF0 + SM_A_BYTES);
    cp_async_arrive(sb + 0);
    load_A(sb + SM_BUF0 + STAGE_BYTES);
    load_B(sb + SM_BUF0 + STAGE_BYTES + SM_A_BYTES);
    cp_async_arrive(sb + 8);

    // A fragment float4-indices (within stage A region), per (mt,k16)
    const int sgq = ((gq & 1) << 2) ^ ((gq >> 1) & 3);
    int rowp[4][2];
#pragma unroll
    for (int mt = 0; mt < 4; ++mt)
#pragma unroll
        for (int k16 = 0; k16 < 2; ++k16)
            rowp[mt][k16] = (wm * 64 + mt * 16 + gq) * 8 + ((4 * k16 + tg) ^ sgq);

    float c[4][8][4];
#pragma unroll
    for (int mt = 0; mt < 4; ++mt)
#pragma unroll
        for (int nt = 0; nt < 8; ++nt)
#pragma unroll
            for (int j = 0; j < 4; ++j) c[mt][nt][j] = 0.0f;

    for (int ko = 0; ko < NK; ko += 4) {
        const uint32_t op = (uint32_t)((ko >> 2) & 1);
        const uint32_t opx = op ^ 1u;
#pragma unroll
        for (int si = 0; si < 4; ++si) {
            const int kt = ko + si;
            mbar_wait(sb + si * 8, op);               // full[si]

            const float4* sA = reinterpret_cast<const float4*>(
                smem + SM_BUF0 + (size_t)(si * STAGE_BYTES));
            const float4* sB = reinterpret_cast<const float4*>(
                smem + SM_BUF0 + (size_t)(si * STAGE_BYTES) + SM_A_BYTES);

            const int s2 = (si + 2) & 3;
            const uint32_t s2base = sb + SM_BUF0 + (uint32_t)(s2 * STAGE_BYTES);
            const bool more2 = (kt + 2 < NK);
            const uint32_t ep = (si < 2) ? opx : op;

#pragma unroll
            for (int k16 = 0; k16 < 2; ++k16) {
                // A fragments: rows g and g+8, one LDS.128 each per mt,
                // covering both k8-steps of this k16 group (k-permuted).
                float4 ag[4], ah[4];
#pragma unroll
                for (int mt = 0; mt < 4; ++mt) {
                    ag[mt] = sA[rowp[mt][k16]];
                    ah[mt] = sA[rowp[mt][k16] + 64];   // +8 rows
                }
                float4 bf[8];
#pragma unroll
                for (int nt = 0; nt < 8; ++nt)
                    bf[nt] = sB[(((wn * 8 + nt) * 2 + k16) * 32) + lane];
                // j=0 (k = 4t, 4t+1)
#pragma unroll
                for (int nt = 0; nt < 8; ++nt) {
                    uint32_t b0 = __float_as_uint(bf[nt].x);
                    uint32_t b1 = __float_as_uint(bf[nt].y);
#pragma unroll
                    for (int mt = 0; mt < 4; ++mt) {
                        mma_tf32(c[mt][nt][0], c[mt][nt][1],
                                 c[mt][nt][2], c[mt][nt][3],
                                 __float_as_uint(ag[mt].x), __float_as_uint(ah[mt].x),
                                 __float_as_uint(ag[mt].y), __float_as_uint(ah[mt].y),
                                 b0, b1);
                    }
                }
                // j=1 (k = 4t+2, 4t+3)
#pragma unroll
                for (int nt = 0; nt < 8; ++nt) {
                    uint32_t b0 = __float_as_uint(bf[nt].z);
                    uint32_t b1 = __float_as_uint(bf[nt].w);
#pragma unroll
                    for (int mt = 0; mt < 4; ++mt) {
                        mma_tf32(c[mt][nt][0], c[mt][nt][1],
                                 c[mt][nt][2], c[mt][nt][3],
                                 __float_as_uint(ag[mt].z), __float_as_uint(ah[mt].z),
                                 __float_as_uint(ag[mt].w), __float_as_uint(ah[mt].w),
                                 b0, b1);
                    }
                }
                // interleaved refill for kt+2
                if (k16 == 0 && more2) {
                    if (kt >= 2)
                        mbar_wait(sb + 32 + s2 * 8, ep);   // empty[s2]
                    load_A(s2base);
                }
                if (k16 == 1 && more2) {
                    load_B(s2base + SM_A_BYTES);
                    cp_async_arrive(sb + s2 * 8);          // full[s2]
                }
            }

            if (lane == 0) mbar_arrive(sb + 32 + si * 8);  // empty[si]
        }
    }

    // ---- epilogue: bias + store ----
#pragma unroll
    for (int mt = 0; mt < 4; ++mt) {
        const int row0 = m0 + wm * 64 + mt * 16 + gq;
#pragma unroll
        for (int nt = 0; nt < 8; ++nt) {
            const int col = n0 + wn * 64 + nt * 8 + 2 * tg;
            const float2 bv = *reinterpret_cast<const float2*>(g_bias + col);
            float2 v0, v1;
            v0.x = c[mt][nt][0] + bv.x;
            v0.y = c[mt][nt][1] + bv.y;
            v1.x = c[mt][nt][2] + bv.x;
            v1.y = c[mt][nt][3] + bv.y;
            *reinterpret_cast<float2*>(out + (size_t)row0 * OUT_F + col) = v0;
            *reinterpret_cast<float2*>(out + (size_t)(row0 + 8) * OUT_F + col) = v1;
        }
    }
}

// ============================================================
// Launch
// ============================================================
extern "C" void kernel_launch(void* const* d_in, const int* in_sizes, int n_in,
                              void* d_out, int out_size) {
    const float* x    = (const float*)d_in[0];
    const float* wmu  = (const float*)d_in[1];
    const float* wlv  = (const float*)d_in[2];
    const float* bmu  = (const float*)d_in[3];
    const float* blv  = (const float*)d_in[4];
    const float* weps = (const float*)d_in[5];
    const float* beps = (const float*)d_in[6];
    float* out = (float*)d_out;

    prep_fused<<<PREP_BLOCKS, 256>>>(wmu, wlv, weps, bmu, blv, beps);

    cudaFuncSetAttribute(gemm_kernel,
                         cudaFuncAttributeMaxDynamicSharedMemorySize, SMEM_TOTAL);
    gemm_kernel<<<NPM * NPN, THREADS, SMEM_TOTAL>>>(x, out);
}

// round 17
// speedup vs baseline: 1.2779x; 1.2779x over previous
#include <cuda_runtime.h>
#include <cuda_bf16.h>
#include <stdint.h>

// ============================================================
// Problem dims
// ============================================================
#define IN_F  4096
#define OUT_F 4096
#define BATCH 8192

#define BM 256
#define BN 128
#define BK 32
#define NK (IN_F / BK)          // 128 k-tiles
#define NPM (BATCH / BM)        // 32
#define NPN (OUT_F / BN)        // 32
#define TILE_GROUP 8
#define THREADS 256             // 8 warps: 4 (M) x 2 (N), warp tile 64x64
#define STAGES 4

#define NK8  (IN_F / 8)         // 512 kk-groups per row (2 per k16)
#define NK16 (IN_F / 16)        // 256 k16 groups per row

// SMEM: [0..32) full mbar[4], [32..64) empty mbar[4], buffers at 128
#define SM_BUF0 128
#define SM_A_BYTES 32768
#define SM_B_BYTES 16384
#define STAGE_BYTES (SM_A_BYTES + SM_B_BYTES)        // 49152
#define SMEM_TOTAL (SM_BUF0 + STAGES * STAGE_BYTES)  // 196736

// per-refill global byte advance
#define A_STEP 2048u
#define B_STEP 1024u

// fused prep block ranges (256 threads each)
#define PREP_X_BLOCKS 16384     // 4.19M threads: (row16, k16, lane)
#define PREP_W_BLOCKS 16384
#define PREP_BLOCKS (PREP_X_BLOCKS + PREP_W_BLOCKS + 16)

// ============================================================
// Scratch
// XP[row16][kk=2*k16+j][lane(g,t)] = (x[g][K], x[g+8][K], x[g][K+1], x[g+8][K+1]),
//   K = k16*16 + 4t + 2j   (k-permuted fragment order)
// WP[col8][k16][lane(g,t)] = w[n=col8*8+g][k16*16+4t .. 4t+3]
// ============================================================
__device__ float4 g_XP[(size_t)(BATCH / 16) * NK8 * 32];
__device__ float4 g_WP[(size_t)(OUT_F / 8) * NK16 * 32];
__device__ float  g_bias[OUT_F];

// ============================================================
// Helpers
// ============================================================
__device__ __forceinline__ float rnd_tf32(float f) {
    float r;
    asm("cvt.rna.tf32.f32 %0, %1;" : "=f"(r) : "f"(f));
    return r;
}

__device__ __forceinline__ uint32_t smem_u32(const void* p) {
    uint32_t a;
    asm("{ .reg .u64 t; cvta.to.shared.u64 t, %1; cvt.u32.u64 %0, t; }"
        : "=r"(a) : "l"(p));
    return a;
}

__device__ __forceinline__ void cp16(uint32_t saddr, const void* gptr) {
    asm volatile("cp.async.cg.shared.global [%0], [%1], 16;\n"
                 :: "r"(saddr), "l"(gptr));
}

__device__ __forceinline__ void mbar_init(uint32_t a, uint32_t cnt) {
    asm volatile("mbarrier.init.shared.b64 [%0], %1;" :: "r"(a), "r"(cnt) : "memory");
}
__device__ __forceinline__ void mbar_arrive(uint32_t a) {
    asm volatile("mbarrier.arrive.shared.b64 _, [%0];" :: "r"(a) : "memory");
}
__device__ __forceinline__ void mbar_wait(uint32_t addr, uint32_t parity) {
    asm volatile(
        "{\n\t.reg .pred P;\n\t"
        "WAIT_%=:\n\t"
        "mbarrier.try_wait.parity.acquire.cta.shared::cta.b64 P, [%0], %1, 0x989680;\n\t"
        "@P bra.uni DONE_%=;\n\t"
        "bra.uni WAIT_%=;\n\t"
        "DONE_%=:\n\t}"
        :: "r"(addr), "r"(parity) : "memory");
}
__device__ __forceinline__ void cp_async_arrive(uint32_t a) {
    asm volatile("cp.async.mbarrier.arrive.noinc.shared.b64 [%0];"
                 :: "r"(a) : "memory");
}

__device__ __forceinline__ void mma_tf32(float& c0, float& c1, float& c2, float& c3,
                                         uint32_t a0, uint32_t a1, uint32_t a2, uint32_t a3,
                                         uint32_t b0, uint32_t b1) {
    asm volatile(
        "mma.sync.aligned.m16n8k8.row.col.f32.tf32.tf32.f32 "
        "{%0,%1,%2,%3}, {%4,%5,%6,%7}, {%8,%9}, {%0,%1,%2,%3};"
        : "+f"(c0), "+f"(c1), "+f"(c2), "+f"(c3)
        : "r"(a0), "r"(a1), "r"(a2), "r"(a3), "r"(b0), "r"(b1));
}

// ============================================================
// Fused prep, fully coalesced reads AND writes:
//  X: thread <-> (row16, k16, lane); 2 float4 reads (rows g, g+8),
//     component shuffle, 2 float4 writes (kk = 2*k16, 2*k16+1).
//  W: R16-style float4 materialize+pack (verified correct).
// ============================================================
__global__ void prep_fused(const float* __restrict__ x,
                           const float* __restrict__ mu,
                           const float* __restrict__ lv,
                           const float* __restrict__ eps,
                           const float* __restrict__ bmu,
                           const float* __restrict__ blv,
                           const float* __restrict__ beps) {
    int bid = blockIdx.x;
    if (bid < PREP_X_BLOCKS) {
        size_t i = (size_t)bid * 256 + threadIdx.x;          // 4194304
        int row16 = (int)(i >> 13);                          // / (256*32)
        int rem   = (int)(i & 8191);
        int k16   = rem >> 5;
        int lane  = rem & 31;
        int g = lane >> 2, t = lane & 3;
        const float4* x4 = reinterpret_cast<const float4*>(x);
        float4 xg = x4[(size_t)(row16 * 16 + g) * (IN_F / 4) + k16 * 4 + t];
        float4 xh = x4[(size_t)(row16 * 16 + g + 8) * (IN_F / 4) + k16 * 4 + t];
        float4 v0, v1;
        v0.x = rnd_tf32(xg.x); v0.y = rnd_tf32(xh.x);
        v0.z = rnd_tf32(xg.y); v0.w = rnd_tf32(xh.y);
        v1.x = rnd_tf32(xg.z); v1.y = rnd_tf32(xh.z);
        v1.z = rnd_tf32(xg.w); v1.w = rnd_tf32(xh.w);
        size_t o = ((size_t)row16 * NK8 + 2 * k16) * 32 + lane;
        g_XP[o]      = v0;     // kk = 2*k16   (j=0: K=4t, 4t+1)
        g_XP[o + 32] = v1;     // kk = 2*k16+1 (j=1: K=4t+2, 4t+3)
    } else if (bid < PREP_X_BLOCKS + PREP_W_BLOCKS) {
        size_t i = (size_t)(bid - PREP_X_BLOCKS) * 256 + threadIdx.x;  // 4194304
        int col8 = (int)(i >> 13);
        int rem  = (int)(i & 8191);
        int k16  = rem >> 5;
        int lane = rem & 31;
        int g = lane >> 2, t = lane & 3;
        size_t idx4 = (size_t)(col8 * 8 + g) * (IN_F / 4) + k16 * 4 + t;
        float4 m4 = reinterpret_cast<const float4*>(mu)[idx4];
        float4 l4 = reinterpret_cast<const float4*>(lv)[idx4];
        float4 e4 = reinterpret_cast<const float4*>(eps)[idx4];
        float4 v;
        v.x = rnd_tf32(m4.x + e4.x * __expf(0.5f * l4.x));
        v.y = rnd_tf32(m4.y + e4.y * __expf(0.5f * l4.y));
        v.z = rnd_tf32(m4.z + e4.z * __expf(0.5f * l4.z));
        v.w = rnd_tf32(m4.w + e4.w * __expf(0.5f * l4.w));
        g_WP[i] = v;
    } else {
        int i = (bid - PREP_X_BLOCKS - PREP_W_BLOCKS) * 256 + threadIdx.x;
        if (i < OUT_F) g_bias[i] = bmu[i] + beps[i] * __expf(0.5f * blv[i]);
    }
}

// ============================================================
// GEMM: C[256,128] per CTA, 256 threads (8 warps = 4 x 2)
// warp tile 64 x 64, BK=32, 4-stage pipeline, refill 2 ahead,
// mainloop unrolled x4. EXACT R12 champion structure; only the
// packed-array contents (k permutation) differ, which is
// invisible to the instruction stream.
// ============================================================
__global__ void __launch_bounds__(THREADS, 1) gemm_kernel(float* __restrict__ out) {
    extern __shared__ char smem[];
    const uint32_t sb = smem_u32(smem);
    const int tid = threadIdx.x;
    const int wid = tid >> 5;
    const int lane = tid & 31;
    const int wm = wid >> 1;      // 0..3  (M, 64 rows)
    const int wn = wid & 1;       // 0..1  (N, 64 cols)
    const int gq = lane >> 2;
    const int tg = lane & 3;

    int pid = blockIdx.x;
    int grp = pid / (TILE_GROUP * NPN);
    int pin = pid % (TILE_GROUP * NPN);
    int pm  = grp * TILE_GROUP + (pin % TILE_GROUP);
    int pn  = pin / TILE_GROUP;
    const int m0 = pm * BM;
    const int n0 = pn * BN;
    const int m016 = m0 >> 4;
    const int n08  = n0 >> 3;

    if (tid == 0) {
#pragma unroll
        for (int s = 0; s < STAGES; ++s) {
            mbar_init(sb + s * 8, 256);
            mbar_init(sb + 32 + s * 8, 8);
        }
    }
    __syncthreads();

    // ---- strength-reduced refill offsets ----
    uint32_t offA[8], offB[4];
#pragma unroll
    for (int t = 0; t < 8; ++t) {
        int ca = tid + t * THREADS;
        int r16l = ca >> 7;
        int inner = ca & 127;
        offA[t] = (uint32_t)(((((m016 + r16l) * NK8) + (inner >> 5)) * 32
                              + (inner & 31)) * 16);
    }
#pragma unroll
    for (int t = 0; t < 4; ++t) {
        int cb = tid + t * THREADS;
        int c8l = cb >> 6;
        int inner = cb & 63;
        offB[t] = (uint32_t)(((((n08 + c8l) * NK16) + (inner >> 5)) * 32
                              + (inner & 31)) * 16);
    }
    const char* gXb = (const char*)g_XP;
    const char* gWb = (const char*)g_WP;

    auto load_A = [&](uint32_t abase) {
#pragma unroll
        for (int t = 0; t < 8; ++t)
            cp16(abase + (uint32_t)(tid + t * THREADS) * 16u, gXb + offA[t]);
#pragma unroll
        for (int t = 0; t < 8; ++t) offA[t] += A_STEP;
    };
    auto load_B = [&](uint32_t bbase) {
#pragma unroll
        for (int t = 0; t < 4; ++t)
            cp16(bbase + (uint32_t)(tid + t * THREADS) * 16u, gWb + offB[t]);
#pragma unroll
        for (int t = 0; t < 4; ++t) offB[t] += B_STEP;
    };

    // prologue: load stages 0 and 1
    load_A(sb + SM_BUF0);
    load_B(sb + SM_BUF0 + SM_A_BYTES);
    cp_async_arrive(sb + 0);
    load_A(sb + SM_BUF0 + STAGE_BYTES);
    load_B(sb + SM_BUF0 + STAGE_BYTES + SM_A_BYTES);
    cp_async_arrive(sb + 8);

    float c[4][8][4];
#pragma unroll
    for (int mt = 0; mt < 4; ++mt)
#pragma unroll
        for (int nt = 0; nt < 8; ++nt)
#pragma unroll
            for (int j = 0; j < 4; ++j) c[mt][nt][j] = 0.0f;

    for (int ko = 0; ko < NK; ko += 4) {
        const uint32_t op = (uint32_t)((ko >> 2) & 1);
        const uint32_t opx = op ^ 1u;
#pragma unroll
        for (int si = 0; si < 4; ++si) {
            const int kt = ko + si;
            mbar_wait(sb + si * 8, op);               // full[si]

            const float4* sA = reinterpret_cast<const float4*>(
                smem + SM_BUF0 + (size_t)(si * STAGE_BYTES));
            const float4* sB = reinterpret_cast<const float4*>(
                smem + SM_BUF0 + (size_t)(si * STAGE_BYTES) + SM_A_BYTES);

            const int s2 = (si + 2) & 3;
            const uint32_t s2base = sb + SM_BUF0 + (uint32_t)(s2 * STAGE_BYTES);
            const bool more2 = (kt + 2 < NK);
            const uint32_t ep = (si < 2) ? opx : op;

#pragma unroll
            for (int k16 = 0; k16 < 2; ++k16) {
                // kk2 = 0: A fragments from kk = 2*k16 (j=0), B (x,y)
                float4 af[4];
#pragma unroll
                for (int mt = 0; mt < 4; ++mt)
                    af[mt] = sA[(((wm * 4 + mt) * 4 + k16 * 2) * 32) + lane];
                float4 bf[8];
#pragma unroll
                for (int nt = 0; nt < 8; ++nt) {
                    bf[nt] = sB[(((wn * 8 + nt) * 2 + k16) * 32) + lane];
                    uint32_t b0 = __float_as_uint(bf[nt].x);
                    uint32_t b1 = __float_as_uint(bf[nt].y);
#pragma unroll
                    for (int mt = 0; mt < 4; ++mt) {
                        mma_tf32(c[mt][nt][0], c[mt][nt][1],
                                 c[mt][nt][2], c[mt][nt][3],
                                 __float_as_uint(af[mt].x), __float_as_uint(af[mt].y),
                                 __float_as_uint(af[mt].z), __float_as_uint(af[mt].w),
                                 b0, b1);
                    }
                }
                // kk2 = 1: A fragments from kk = 2*k16+1 (j=1), B (z,w)
#pragma unroll
                for (int mt = 0; mt < 4; ++mt)
                    af[mt] = sA[(((wm * 4 + mt) * 4 + k16 * 2 + 1) * 32) + lane];
#pragma unroll
                for (int nt = 0; nt < 8; ++nt) {
                    uint32_t b0 = __float_as_uint(bf[nt].z);
                    uint32_t b1 = __float_as_uint(bf[nt].w);
#pragma unroll
                    for (int mt = 0; mt < 4; ++mt) {
                        mma_tf32(c[mt][nt][0], c[mt][nt][1],
                                 c[mt][nt][2], c[mt][nt][3],
                                 __float_as_uint(af[mt].x), __float_as_uint(af[mt].y),
                                 __float_as_uint(af[mt].z), __float_as_uint(af[mt].w),
                                 b0, b1);
                    }
                }
                // interleaved refill for kt+2
                if (k16 == 0 && more2) {
                    if (kt >= 2)
                        mbar_wait(sb + 32 + s2 * 8, ep);   // empty[s2]
                    load_A(s2base);
                }
                if (k16 == 1 && more2) {
                    load_B(s2base + SM_A_BYTES);
                    cp_async_arrive(sb + s2 * 8);          // full[s2]
                }
            }

            if (lane == 0) mbar_arrive(sb + 32 + si * 8);  // empty[si]
        }
    }

    // ---- epilogue: bias + store ----
#pragma unroll
    for (int mt = 0; mt < 4; ++mt) {
        const int row0 = m0 + wm * 64 + mt * 16 + gq;
#pragma unroll
        for (int nt = 0; nt < 8; ++nt) {
            const int col = n0 + wn * 64 + nt * 8 + 2 * tg;
            const float2 bv = *reinterpret_cast<const float2*>(g_bias + col);
            float2 v0, v1;
            v0.x = c[mt][nt][0] + bv.x;
            v0.y = c[mt][nt][1] + bv.y;
            v1.x = c[mt][nt][2] + bv.x;
            v1.y = c[mt][nt][3] + bv.y;
            *reinterpret_cast<float2*>(out + (size_t)row0 * OUT_F + col) = v0;
            *reinterpret_cast<float2*>(out + (size_t)(row0 + 8) * OUT_F + col) = v1;
        }
    }
}

// ============================================================
// Launch
// ============================================================
extern "C" void kernel_launch(void* const* d_in, const int* in_sizes, int n_in,
                              void* d_out, int out_size) {
    const float* x    = (const float*)d_in[0];
    const float* wmu  = (const float*)d_in[1];
    const float* wlv  = (const float*)d_in[2];
    const float* bmu  = (const float*)d_in[3];
    const float* blv  = (const float*)d_in[4];
    const float* weps = (const float*)d_in[5];
    const float* beps = (const float*)d_in[6];
    float* out = (float*)d_out;

    prep_fused<<<PREP_BLOCKS, 256>>>(x, wmu, wlv, weps, bmu, blv, beps);

    cudaFuncSetAttribute(gemm_kernel,
                         cudaFuncAttributeMaxDynamicSharedMemorySize, SMEM_TOTAL);
    gemm_kernel<<<NPM * NPN, THREADS, SMEM_TOTAL>>>(out);
}